// round 1
// baseline (speedup 1.0000x reference)
#include <cuda_runtime.h>
#include <math_constants.h>

#define FDIM 128
#define NMAX 100096
#define EMAX 600064

// Scratch (device globals: allocation-free contract)
__device__ float g_xl[NMAX * FDIM];   // x_low @ W_l
__device__ float g_xr[NMAX * FDIM];   // x_high @ W_r
__device__ int   g_csr_src[EMAX];     // src node per CSR slot (grouped by dst)
__device__ int   g_deg[NMAX];
__device__ int   g_off[NMAX];
__device__ int   g_cur[NMAX];
__device__ int   g_part[NMAX];
__device__ int   g_bsum[1024];

// ---------------------------------------------------------------------------
// GEMM: O[M,128] = A[M,128] @ W[128,128], fp32.
// Block tile 128x128, 256 threads, 8x8 micro-tile (cols split c0 / c0+64 so
// LDS.128 b-loads are phase-contiguous -> conflict-free).
// ---------------------------------------------------------------------------
__global__ void gemm_kernel(const float* __restrict__ A,
                            const float* __restrict__ W,
                            float* __restrict__ O, int M) {
    extern __shared__ float smem[];
    float* sA = smem;              // [128][128]
    float* sW = smem + 128 * 128;  // [128][128]
    const int tid  = threadIdx.x;
    const int row0 = blockIdx.x * 128;

    // Load tiles: 4096 float4 each, 16 per thread, fully coalesced.
#pragma unroll
    for (int it = 0; it < 16; ++it) {
        int i = it * 256 + tid;
        int r = i >> 5, c = i & 31;
        int gr = row0 + r;
        float4 v = make_float4(0.f, 0.f, 0.f, 0.f);
        if (gr < M) v = reinterpret_cast<const float4*>(A)[gr * 32 + c];
        reinterpret_cast<float4*>(sA)[i] = v;
        reinterpret_cast<float4*>(sW)[i] = reinterpret_cast<const float4*>(W)[i];
    }
    __syncthreads();

    const int tx = tid & 15;   // 16 col groups
    const int ty = tid >> 4;   // 16 row groups
    const int r0 = ty * 8;
    const int c0 = tx * 4;     // cols [c0..c0+3] and [c0+64..c0+67]

    float acc[8][8];
#pragma unroll
    for (int i = 0; i < 8; i++)
#pragma unroll
        for (int j = 0; j < 8; j++) acc[i][j] = 0.f;

#pragma unroll 4
    for (int k = 0; k < 128; k++) {
        float b[8];
        *reinterpret_cast<float4*>(&b[0]) =
            *reinterpret_cast<const float4*>(&sW[k * 128 + c0]);
        *reinterpret_cast<float4*>(&b[4]) =
            *reinterpret_cast<const float4*>(&sW[k * 128 + c0 + 64]);
        float a[8];
#pragma unroll
        for (int i = 0; i < 8; i++) a[i] = sA[(r0 + i) * 128 + k];  // broadcast
#pragma unroll
        for (int i = 0; i < 8; i++)
#pragma unroll
            for (int j = 0; j < 8; j++) acc[i][j] += a[i] * b[j];
    }

#pragma unroll
    for (int i = 0; i < 8; i++) {
        int gr = row0 + r0 + i;
        if (gr < M) {
            reinterpret_cast<float4*>(O)[gr * 32 + (c0 >> 2)] =
                make_float4(acc[i][0], acc[i][1], acc[i][2], acc[i][3]);
            reinterpret_cast<float4*>(O)[gr * 32 + 16 + (c0 >> 2)] =
                make_float4(acc[i][4], acc[i][5], acc[i][6], acc[i][7]);
        }
    }
}

// ---------------------------------------------------------------------------
// CSR construction
// ---------------------------------------------------------------------------
__global__ void zero2_kernel(int* a, int* b, int n) {
    int i = blockIdx.x * blockDim.x + threadIdx.x;
    if (i < n) { a[i] = 0; b[i] = 0; }
}

__global__ void hist_kernel(const int* __restrict__ dst, int* deg, int E) {
    int i = blockIdx.x * blockDim.x + threadIdx.x;
    if (i < E) atomicAdd(&deg[dst[i]], 1);
}

// Per-block exclusive scan (512) + block totals
__global__ void scan1_kernel(const int* __restrict__ in, int* out, int* bsum, int n) {
    __shared__ int s[512];
    int t = threadIdx.x;
    int i = blockIdx.x * 512 + t;
    int v = (i < n) ? in[i] : 0;
    s[t] = v;
    __syncthreads();
    for (int off = 1; off < 512; off <<= 1) {
        int add = (t >= off) ? s[t - off] : 0;
        __syncthreads();
        s[t] += add;
        __syncthreads();
    }
    if (i < n) out[i] = s[t] - v;            // exclusive
    if (t == 511) bsum[blockIdx.x] = s[511]; // inclusive total
}

// Single-block exclusive scan of block sums (nblk <= 1024)
__global__ void scan2_kernel(int* bsum, int nblk) {
    __shared__ int s[1024];
    int t = threadIdx.x;
    int v = (t < nblk) ? bsum[t] : 0;
    s[t] = v;
    __syncthreads();
    for (int off = 1; off < 1024; off <<= 1) {
        int add = (t >= off) ? s[t - off] : 0;
        __syncthreads();
        s[t] += add;
        __syncthreads();
    }
    if (t < nblk) bsum[t] = s[t] - v;
}

__global__ void scan3_kernel(const int* __restrict__ part,
                             const int* __restrict__ bsum,
                             int* off, int n) {
    int i = blockIdx.x * blockDim.x + threadIdx.x;
    if (i < n) off[i] = part[i] + bsum[i >> 9];
}

__global__ void scatter_kernel(const int* __restrict__ esrc,
                               const int* __restrict__ edst,
                               const int* __restrict__ off,
                               int* cur, int* csr_src, int E) {
    int i = blockIdx.x * blockDim.x + threadIdx.x;
    if (i >= E) return;
    int d = edst[i];
    int p = off[d] + atomicAdd(&cur[d], 1);
    csr_src[p] = esrc[i];
}

// ---------------------------------------------------------------------------
// Aggregate: one warp per dst node, online softmax, single xj gather per edge.
// out[d,:] = (sum_e softmax(e)_e * xj_e) / deg + bias
// ---------------------------------------------------------------------------
__global__ void aggregate_kernel(const int* __restrict__ off,
                                 const int* __restrict__ deg,
                                 const int* __restrict__ csr_src,
                                 const float* __restrict__ xl,
                                 const float* __restrict__ xr,
                                 const float* __restrict__ att,
                                 const float* __restrict__ bias,
                                 float* __restrict__ out, int N) {
    int w    = (blockIdx.x * blockDim.x + threadIdx.x) >> 5;
    int lane = threadIdx.x & 31;
    if (w >= N) return;

    float4 b4 = reinterpret_cast<const float4*>(bias)[lane];
    int cnt = deg[w];
    if (cnt == 0) {
        reinterpret_cast<float4*>(out)[w * 32 + lane] = b4;
        return;
    }
    int start = off[w];
    float4 a4 = reinterpret_cast<const float4*>(att)[lane];
    float4 xi = reinterpret_cast<const float4*>(xr)[w * 32 + lane];

    float m = -3.4e38f, denom = 0.f;
    float4 acc = make_float4(0.f, 0.f, 0.f, 0.f);

    for (int j = 0; j < cnt; ++j) {
        int p = start + j;
        int s = csr_src[p];
        float4 xj = reinterpret_cast<const float4*>(xl)[s * 32 + lane];
        float vx = xi.x + xj.x; vx = vx > 0.f ? vx : 0.2f * vx;
        float vy = xi.y + xj.y; vy = vy > 0.f ? vy : 0.2f * vy;
        float vz = xi.z + xj.z; vz = vz > 0.f ? vz : 0.2f * vz;
        float vw = xi.w + xj.w; vw = vw > 0.f ? vw : 0.2f * vw;
        float e = a4.x * vx + a4.y * vy + a4.z * vz + a4.w * vw;
#pragma unroll
        for (int o = 16; o; o >>= 1) e += __shfl_xor_sync(0xffffffffu, e, o);
        // online softmax rescale
        float mn   = fmaxf(m, e);
        float cold = __expf(m - mn);   // 0 on first iter (m = -3.4e38)
        float cnew = __expf(e - mn);
        denom = denom * cold + cnew;
        acc.x = acc.x * cold + cnew * xj.x;
        acc.y = acc.y * cold + cnew * xj.y;
        acc.z = acc.z * cold + cnew * xj.z;
        acc.w = acc.w * cold + cnew * xj.w;
        m = mn;
    }

    float scale = 1.f / (fmaxf(denom, 1e-16f) * (float)cnt);
    reinterpret_cast<float4*>(out)[w * 32 + lane] =
        make_float4(acc.x * scale + b4.x, acc.y * scale + b4.y,
                    acc.z * scale + b4.z, acc.w * scale + b4.w);
}

// ---------------------------------------------------------------------------
extern "C" void kernel_launch(void* const* d_in, const int* in_sizes, int n_in,
                              void* d_out, int out_size) {
    const float* x_low  = (const float*)d_in[0];
    const float* x_high = (const float*)d_in[1];
    const float* W_l    = (const float*)d_in[2];
    const float* W_r    = (const float*)d_in[3];
    const float* att    = (const float*)d_in[4];
    const float* bias   = (const float*)d_in[5];
    const int*   esrc   = (const int*)d_in[6];
    const int*   edst   = (const int*)d_in[7];
    int Nlow  = in_sizes[0] / FDIM;
    int Nhigh = in_sizes[1] / FDIM;
    int E     = in_sizes[6];
    float* out = (float*)d_out;

    float *xl, *xr;
    int *csrs, *deg, *off, *cur, *part, *bsum;
    cudaGetSymbolAddress((void**)&xl,   g_xl);
    cudaGetSymbolAddress((void**)&xr,   g_xr);
    cudaGetSymbolAddress((void**)&csrs, g_csr_src);
    cudaGetSymbolAddress((void**)&deg,  g_deg);
    cudaGetSymbolAddress((void**)&off,  g_off);
    cudaGetSymbolAddress((void**)&cur,  g_cur);
    cudaGetSymbolAddress((void**)&part, g_part);
    cudaGetSymbolAddress((void**)&bsum, g_bsum);

    const int GEMM_SMEM = 2 * 128 * 128 * (int)sizeof(float);  // 128 KB
    cudaFuncSetAttribute(gemm_kernel,
                         cudaFuncAttributeMaxDynamicSharedMemorySize, GEMM_SMEM);

    gemm_kernel<<<(Nlow  + 127) / 128, 256, GEMM_SMEM>>>(x_low,  W_l, xl, Nlow);
    gemm_kernel<<<(Nhigh + 127) / 128, 256, GEMM_SMEM>>>(x_high, W_r, xr, Nhigh);

    zero2_kernel<<<(Nhigh + 255) / 256, 256>>>(deg, cur, Nhigh);
    hist_kernel<<<(E + 255) / 256, 256>>>(edst, deg, E);

    int nblk = (Nhigh + 511) / 512;
    scan1_kernel<<<nblk, 512>>>(deg, part, bsum, Nhigh);
    scan2_kernel<<<1, 1024>>>(bsum, nblk);
    scan3_kernel<<<(Nhigh + 255) / 256, 256>>>(part, bsum, off, Nhigh);

    scatter_kernel<<<(E + 255) / 256, 256>>>(esrc, edst, off, cur, csrs, E);

    aggregate_kernel<<<(Nhigh + 7) / 8, 256>>>(off, deg, csrs, xl, xr,
                                               att, bias, out, Nhigh);
}

// round 4
// speedup vs baseline: 1.3910x; 1.3910x over previous
#include <cuda_runtime.h>
#include <cuda_bf16.h>
#include <cstdint>

#define FDIM 128
#define NMAX 100096
#define EMAX 600064

// ---------------- device-global scratch (allocation-free contract) ----------
__device__ float g_xl[NMAX * FDIM];   // x_low @ W_l
__device__ float g_xr[NMAX * FDIM];   // x_high @ W_r
__device__ int   g_csr_src[EMAX];
__device__ int   g_deg[NMAX];
__device__ int   g_off[NMAX];
__device__ int   g_cur[NMAX];
__device__ int   g_part[NMAX];
__device__ int   g_bsum[1024];
// Pre-split W^T images, plain [n][k] bf16 (packed as u32 pairs):
// [0]=Wl_hi [1]=Wl_lo [2]=Wr_hi [3]=Wr_lo
__device__ unsigned g_wimg[4][8192];

// ---------------------------------------------------------------------------
// W prep: Wt[n][k] = W[k][n], split into bf16 hi + lo. 2 blocks, 128 thr.
// ---------------------------------------------------------------------------
__global__ void wprep_kernel(const float* __restrict__ Wl,
                             const float* __restrict__ Wr) {
    const float* W = blockIdx.x ? Wr : Wl;
    unsigned* hi = g_wimg[blockIdx.x * 2];
    unsigned* lo = g_wimg[blockIdx.x * 2 + 1];
    int n = threadIdx.x;
#pragma unroll 8
    for (int k = 0; k < 128; k += 2) {
        float v0 = W[k * 128 + n];
        float v1 = W[(k + 1) * 128 + n];
        __nv_bfloat162 h; h.x = __float2bfloat16_rn(v0); h.y = __float2bfloat16_rn(v1);
        float2 hf = __bfloat1622float2(h);
        __nv_bfloat162 l; l.x = __float2bfloat16_rn(v0 - hf.x);
        l.y = __float2bfloat16_rn(v1 - hf.y);
        hi[(n * 128 + k) >> 1] = *reinterpret_cast<unsigned*>(&h);
        lo[(n * 128 + k) >> 1] = *reinterpret_cast<unsigned*>(&l);
    }
}

// ---------------------------------------------------------------------------
// GEMM via mma.sync bf16 2-way split: O = A @ W  (A fp32 [M,128], W [128,128])
// CTA tile 128x128, 8 warps of 32(M)x64(N). Padded smem rows: 136 bf16 = 272B.
// ---------------------------------------------------------------------------
#define PADB 272                        // bytes per padded row
#define AHI_OFF 0
#define ALO_OFF (128 * PADB)
#define BHI_OFF (2 * 128 * PADB)
#define BLO_OFF (3 * 128 * PADB)
#define GSMEM   (4 * 128 * PADB)        // 139264 B

__device__ __forceinline__ void mma_bf16(float* c, const uint32_t* a,
                                         const uint32_t* b) {
    asm volatile(
        "mma.sync.aligned.m16n8k16.row.col.f32.bf16.bf16.f32 "
        "{%0,%1,%2,%3}, {%4,%5,%6,%7}, {%8,%9}, {%0,%1,%2,%3};"
        : "+f"(c[0]), "+f"(c[1]), "+f"(c[2]), "+f"(c[3])
        : "r"(a[0]), "r"(a[1]), "r"(a[2]), "r"(a[3]), "r"(b[0]), "r"(b[1]));
}

__global__ __launch_bounds__(256, 1)
void gemm_mma_kernel(const float* __restrict__ xlow,
                     const float* __restrict__ xhigh,
                     int Nlow, int Nhigh, int nblkA) {
    extern __shared__ char smem[];
    const int tid = threadIdx.x;

    const float* A; float* O; const unsigned *ghi, *glo; int M, row0;
    if ((int)blockIdx.x < nblkA) {
        A = xlow;  O = g_xl; ghi = g_wimg[0]; glo = g_wimg[1];
        M = Nlow;  row0 = blockIdx.x * 128;
    } else {
        A = xhigh; O = g_xr; ghi = g_wimg[2]; glo = g_wimg[3];
        M = Nhigh; row0 = (blockIdx.x - nblkA) * 128;
    }

    // Stage W hi/lo into padded smem: 4096 8B-chunks each, 16 per thread.
#pragma unroll
    for (int it = 0; it < 16; ++it) {
        int i = it * 256 + tid;          // chunk of 4 bf16
        int n = i >> 5, kc = (i & 31) * 8;   // byte offset of k chunk
        *reinterpret_cast<uint2*>(smem + BHI_OFF + n * PADB + kc) =
            reinterpret_cast<const uint2*>(ghi)[i];
        *reinterpret_cast<uint2*>(smem + BLO_OFF + n * PADB + kc) =
            reinterpret_cast<const uint2*>(glo)[i];
    }

    // Stage A: load fp32, split to bf16 hi/lo, store padded.
#pragma unroll
    for (int it = 0; it < 16; ++it) {
        int i = it * 256 + tid;
        int r = i >> 5, c = i & 31;      // float4 chunk c -> k = 4c
        int gr = row0 + r;
        float4 v = (gr < M) ? reinterpret_cast<const float4*>(A)[gr * 32 + c]
                            : make_float4(0.f, 0.f, 0.f, 0.f);
        __nv_bfloat162 h0, h1, l0, l1;
        h0.x = __float2bfloat16_rn(v.x); h0.y = __float2bfloat16_rn(v.y);
        h1.x = __float2bfloat16_rn(v.z); h1.y = __float2bfloat16_rn(v.w);
        float2 f0 = __bfloat1622float2(h0);
        float2 f1 = __bfloat1622float2(h1);
        l0.x = __float2bfloat16_rn(v.x - f0.x); l0.y = __float2bfloat16_rn(v.y - f0.y);
        l1.x = __float2bfloat16_rn(v.z - f1.x); l1.y = __float2bfloat16_rn(v.w - f1.y);
        uint2 hp, lp;
        hp.x = *reinterpret_cast<unsigned*>(&h0); hp.y = *reinterpret_cast<unsigned*>(&h1);
        lp.x = *reinterpret_cast<unsigned*>(&l0); lp.y = *reinterpret_cast<unsigned*>(&l1);
        *reinterpret_cast<uint2*>(smem + AHI_OFF + r * PADB + c * 8) = hp;
        *reinterpret_cast<uint2*>(smem + ALO_OFF + r * PADB + c * 8) = lp;
    }
    __syncthreads();

    const int wid = tid >> 5, lane = tid & 31;
    const int g = lane >> 2, t = lane & 3;
    const int wm = wid >> 1, wn = wid & 1;   // 4 x 2 warp grid
    const int rA0 = wm * 32;                 // warp M origin within tile
    const int nB0 = wn * 64;                 // warp N origin

    float acc[2][8][4];
#pragma unroll
    for (int mt = 0; mt < 2; mt++)
#pragma unroll
        for (int nt = 0; nt < 8; nt++)
#pragma unroll
            for (int q = 0; q < 4; q++) acc[mt][nt][q] = 0.f;

#pragma unroll
    for (int k0 = 0; k0 < 128; k0 += 16) {
        uint32_t ah[2][4], al[2][4];
#pragma unroll
        for (int mt = 0; mt < 2; mt++) {
            int r = rA0 + mt * 16 + g;
            const char* ph = smem + AHI_OFF;
            const char* pl = smem + ALO_OFF;
            int kb = (k0 + 2 * t) * 2;
            ah[mt][0] = *reinterpret_cast<const uint32_t*>(ph + r * PADB + kb);
            ah[mt][1] = *reinterpret_cast<const uint32_t*>(ph + (r + 8) * PADB + kb);
            ah[mt][2] = *reinterpret_cast<const uint32_t*>(ph + r * PADB + kb + 16);
            ah[mt][3] = *reinterpret_cast<const uint32_t*>(ph + (r + 8) * PADB + kb + 16);
            al[mt][0] = *reinterpret_cast<const uint32_t*>(pl + r * PADB + kb);
            al[mt][1] = *reinterpret_cast<const uint32_t*>(pl + (r + 8) * PADB + kb);
            al[mt][2] = *reinterpret_cast<const uint32_t*>(pl + r * PADB + kb + 16);
            al[mt][3] = *reinterpret_cast<const uint32_t*>(pl + (r + 8) * PADB + kb + 16);
        }
        uint32_t bh[8][2], bl[8][2];
#pragma unroll
        for (int nt = 0; nt < 8; nt++) {
            int n = nB0 + nt * 8 + g;
            int kb = (k0 + 2 * t) * 2;
            bh[nt][0] = *reinterpret_cast<const uint32_t*>(smem + BHI_OFF + n * PADB + kb);
            bh[nt][1] = *reinterpret_cast<const uint32_t*>(smem + BHI_OFF + n * PADB + kb + 16);
            bl[nt][0] = *reinterpret_cast<const uint32_t*>(smem + BLO_OFF + n * PADB + kb);
            bl[nt][1] = *reinterpret_cast<const uint32_t*>(smem + BLO_OFF + n * PADB + kb + 16);
        }
#pragma unroll
        for (int mt = 0; mt < 2; mt++)
#pragma unroll
            for (int nt = 0; nt < 8; nt++) {
                mma_bf16(acc[mt][nt], ah[mt], bh[nt]);
                mma_bf16(acc[mt][nt], ah[mt], bl[nt]);
                mma_bf16(acc[mt][nt], al[mt], bh[nt]);
            }
    }

    // Epilogue: c0,c1 -> (row, 2t..2t+1); c2,c3 -> (row+8).
#pragma unroll
    for (int mt = 0; mt < 2; mt++) {
        int r = row0 + rA0 + mt * 16 + g;
#pragma unroll
        for (int nt = 0; nt < 8; nt++) {
            int cc = nB0 + nt * 8 + 2 * t;
            if (r < M)
                *reinterpret_cast<float2*>(O + (size_t)r * 128 + cc) =
                    make_float2(acc[mt][nt][0], acc[mt][nt][1]);
            if (r + 8 < M)
                *reinterpret_cast<float2*>(O + (size_t)(r + 8) * 128 + cc) =
                    make_float2(acc[mt][nt][2], acc[mt][nt][3]);
        }
    }
}

// ---------------------------------------------------------------------------
// CSR construction
// ---------------------------------------------------------------------------
__global__ void zero2_kernel(int* a, int* b, int n) {
    int i = blockIdx.x * blockDim.x + threadIdx.x;
    if (i < n) { a[i] = 0; b[i] = 0; }
}

__global__ void hist_kernel(const int* __restrict__ dst, int* deg, int E) {
    int i = blockIdx.x * blockDim.x + threadIdx.x;
    if (i < E) atomicAdd(&deg[dst[i]], 1);
}

__global__ void scan1_kernel(const int* __restrict__ in, int* out, int* bsum, int n) {
    __shared__ int s[512];
    int t = threadIdx.x;
    int i = blockIdx.x * 512 + t;
    int v = (i < n) ? in[i] : 0;
    s[t] = v;
    __syncthreads();
    for (int off = 1; off < 512; off <<= 1) {
        int add = (t >= off) ? s[t - off] : 0;
        __syncthreads();
        s[t] += add;
        __syncthreads();
    }
    if (i < n) out[i] = s[t] - v;
    if (t == 511) bsum[blockIdx.x] = s[511];
}

__global__ void scan2_kernel(int* bsum, int nblk) {
    __shared__ int s[1024];
    int t = threadIdx.x;
    int v = (t < nblk) ? bsum[t] : 0;
    s[t] = v;
    __syncthreads();
    for (int off = 1; off < 1024; off <<= 1) {
        int add = (t >= off) ? s[t - off] : 0;
        __syncthreads();
        s[t] += add;
        __syncthreads();
    }
    if (t < nblk) bsum[t] = s[t] - v;
}

__global__ void scan3_kernel(const int* __restrict__ part,
                             const int* __restrict__ bsum,
                             int* off, int n) {
    int i = blockIdx.x * blockDim.x + threadIdx.x;
    if (i < n) off[i] = part[i] + bsum[i >> 9];
}

__global__ void scatter_kernel(const int* __restrict__ esrc,
                               const int* __restrict__ edst,
                               const int* __restrict__ off,
                               int* cur, int* csr_src, int E) {
    int i = blockIdx.x * blockDim.x + threadIdx.x;
    if (i >= E) return;
    int d = edst[i];
    int p = off[d] + atomicAdd(&cur[d], 1);
    csr_src[p] = esrc[i];
}

// ---------------------------------------------------------------------------
// Aggregate: one warp per dst node, online softmax, single xj gather per edge.
// ---------------------------------------------------------------------------
__global__ void aggregate_kernel(const int* __restrict__ off,
                                 const int* __restrict__ deg,
                                 const int* __restrict__ csr_src,
                                 const float* __restrict__ xl,
                                 const float* __restrict__ xr,
                                 const float* __restrict__ att,
                                 const float* __restrict__ bias,
                                 float* __restrict__ out, int N) {
    int w    = (blockIdx.x * blockDim.x + threadIdx.x) >> 5;
    int lane = threadIdx.x & 31;
    if (w >= N) return;

    float4 b4 = reinterpret_cast<const float4*>(bias)[lane];
    int cnt = deg[w];
    if (cnt == 0) {
        reinterpret_cast<float4*>(out)[w * 32 + lane] = b4;
        return;
    }
    int start = off[w];
    float4 a4 = reinterpret_cast<const float4*>(att)[lane];
    float4 xi = reinterpret_cast<const float4*>(xr)[w * 32 + lane];

    float m = -3.4e38f, denom = 0.f;
    float4 acc = make_float4(0.f, 0.f, 0.f, 0.f);

    for (int j = 0; j < cnt; ++j) {
        int s = csr_src[start + j];
        float4 xj = reinterpret_cast<const float4*>(xl)[s * 32 + lane];
        float vx = xi.x + xj.x; vx = vx > 0.f ? vx : 0.2f * vx;
        float vy = xi.y + xj.y; vy = vy > 0.f ? vy : 0.2f * vy;
        float vz = xi.z + xj.z; vz = vz > 0.f ? vz : 0.2f * vz;
        float vw = xi.w + xj.w; vw = vw > 0.f ? vw : 0.2f * vw;
        float e = a4.x * vx + a4.y * vy + a4.z * vz + a4.w * vw;
#pragma unroll
        for (int o = 16; o; o >>= 1) e += __shfl_xor_sync(0xffffffffu, e, o);
        float mn   = fmaxf(m, e);
        float cold = __expf(m - mn);
        float cnew = __expf(e - mn);
        denom = denom * cold + cnew;
        acc.x = acc.x * cold + cnew * xj.x;
        acc.y = acc.y * cold + cnew * xj.y;
        acc.z = acc.z * cold + cnew * xj.z;
        acc.w = acc.w * cold + cnew * xj.w;
        m = mn;
    }

    float scale = 1.f / (fmaxf(denom, 1e-16f) * (float)cnt);
    reinterpret_cast<float4*>(out)[w * 32 + lane] =
        make_float4(acc.x * scale + b4.x, acc.y * scale + b4.y,
                    acc.z * scale + b4.z, acc.w * scale + b4.w);
}

// ---------------------------------------------------------------------------
extern "C" void kernel_launch(void* const* d_in, const int* in_sizes, int n_in,
                              void* d_out, int out_size) {
    const float* x_low  = (const float*)d_in[0];
    const float* x_high = (const float*)d_in[1];
    const float* W_l    = (const float*)d_in[2];
    const float* W_r    = (const float*)d_in[3];
    const float* att    = (const float*)d_in[4];
    const float* bias   = (const float*)d_in[5];
    const int*   esrc   = (const int*)d_in[6];
    const int*   edst   = (const int*)d_in[7];
    int Nlow  = in_sizes[0] / FDIM;
    int Nhigh = in_sizes[1] / FDIM;
    int E     = in_sizes[6];
    float* out = (float*)d_out;

    float *xl, *xr;
    int *csrs, *deg, *off, *cur, *part, *bsum;
    cudaGetSymbolAddress((void**)&xl,   g_xl);
    cudaGetSymbolAddress((void**)&xr,   g_xr);
    cudaGetSymbolAddress((void**)&csrs, g_csr_src);
    cudaGetSymbolAddress((void**)&deg,  g_deg);
    cudaGetSymbolAddress((void**)&off,  g_off);
    cudaGetSymbolAddress((void**)&cur,  g_cur);
    cudaGetSymbolAddress((void**)&part, g_part);
    cudaGetSymbolAddress((void**)&bsum, g_bsum);

    cudaFuncSetAttribute(gemm_mma_kernel,
                         cudaFuncAttributeMaxDynamicSharedMemorySize, GSMEM);

    wprep_kernel<<<2, 128>>>(W_l, W_r);

    int nblkA = (Nlow + 127) / 128;
    int nblkB = (Nhigh + 127) / 128;
    gemm_mma_kernel<<<nblkA + nblkB, 256, GSMEM>>>(x_low, x_high, Nlow, Nhigh, nblkA);

    zero2_kernel<<<(Nhigh + 255) / 256, 256>>>(deg, cur, Nhigh);
    hist_kernel<<<(E + 255) / 256, 256>>>(edst, deg, E);

    int nblk = (Nhigh + 511) / 512;
    scan1_kernel<<<nblk, 512>>>(deg, part, bsum, Nhigh);
    scan2_kernel<<<1, 1024>>>(bsum, nblk);
    scan3_kernel<<<(Nhigh + 255) / 256, 256>>>(part, bsum, off, Nhigh);

    scatter_kernel<<<(E + 255) / 256, 256>>>(esrc, edst, off, cur, csrs, E);

    aggregate_kernel<<<(Nhigh + 7) / 8, 256>>>(off, deg, csrs, xl, xr,
                                               att, bias, out, Nhigh);
}